// round 10
// baseline (speedup 1.0000x reference)
#include <cuda_runtime.h>
#include <cstdint>
#include <cstddef>

// Problem shapes (fixed by the dataset)
#define NB 64          // batch
#define NL 512         // sequence length
#define ND 50          // embedding dim
#define NDP 52         // padded dim (multiple of 4, zero-padded)
#define NM 128         // number of measurement kernels
#define LCHUNK 32      // tokens per k_main CTA
#define NCHUNK (NL / LCHUNK)   // 16

// ---------------- device-global scratch (no runtime allocation) ----------------
__device__ float g_w[NB * NL];                 // softmax weights
__device__ float g_kr[NM * NDP];               // normalized kernel_real, padded
__device__ float g_ki[NM * NDP];               // normalized kernel_imag, padded
__device__ float g_v[(size_t)NB * NL * 2 * NDP];      // sqrt(w)-scaled vr|vi per token (~13.6MB)
__device__ float g_part[NCHUNK * NB * NM];     // per-chunk partial sums

// packed f32x2 helpers (Blackwell sm_103a)
__device__ __forceinline__ float2 up2(unsigned long long v) {
    float2 r;
    asm("mov.b64 {%0, %1}, %2;" : "=f"(r.x), "=f"(r.y) : "l"(v));
    return r;
}
#define FMA2(d, a, b) asm("fma.rn.f32x2 %0, %1, %2, %0;" : "+l"(d) : "l"(a), "l"(b))

// ---------------- K0: normalize measurement kernels, pad to NDP ----------------
__global__ void k_norm(const float* __restrict__ kr, const float* __restrict__ ki) {
    int m = threadIdx.x;   // 0..127
    float s = 0.f;
#pragma unroll
    for (int d = 0; d < ND; d++) {
        float a = kr[m * ND + d];
        float b = ki[m * ND + d];
        s = fmaf(a, a, s);
        s = fmaf(b, b, s);
    }
    float rn = rsqrtf(s);
#pragma unroll
    for (int d = 0; d < NDP; d++) {
        g_kr[m * NDP + d] = (d < ND) ? kr[m * ND + d] * rn : 0.f;
        g_ki[m * NDP + d] = (d < ND) ? ki[m * ND + d] * rn : 0.f;
    }
}

// ---------------- K1: softmax over sequence dim per batch ----------------
__global__ void k_softmax(const int* __restrict__ x, const float* __restrict__ mix) {
    int b = blockIdx.x;          // 0..63
    int t = threadIdx.x;         // 0..511
    float v = mix[x[b * NL + t]];

    __shared__ float red[16];

    // block max
    float m = v;
#pragma unroll
    for (int o = 16; o > 0; o >>= 1) m = fmaxf(m, __shfl_xor_sync(0xffffffffu, m, o));
    if ((t & 31) == 0) red[t >> 5] = m;
    __syncthreads();
    if (t < 16) {
        float mm = red[t];
#pragma unroll
        for (int o = 8; o > 0; o >>= 1) mm = fmaxf(mm, __shfl_xor_sync(0x0000ffffu, mm, o));
        if (t == 0) red[0] = mm;
    }
    __syncthreads();
    float vmax = red[0];
    __syncthreads();

    // block sum of exp
    float e = __expf(v - vmax);
    float s = e;
#pragma unroll
    for (int o = 16; o > 0; o >>= 1) s += __shfl_xor_sync(0xffffffffu, s, o);
    if ((t & 31) == 0) red[t >> 5] = s;
    __syncthreads();
    if (t < 16) {
        float ss = red[t];
#pragma unroll
        for (int o = 8; o > 0; o >>= 1) ss += __shfl_xor_sync(0x0000ffffu, ss, o);
        if (t == 0) red[0] = ss;
    }
    __syncthreads();
    g_w[b * NL + t] = e / red[0];
}

// ---------------- K2: gather + convert: v = sqrt(w) * amp * exp(i*pha) ----------------
// one warp per token; d = lane and lane+32 (D=50), pad d=50,51 with zeros
__global__ void k_gather(const int* __restrict__ x,
                         const float* __restrict__ amp,
                         const float* __restrict__ pha) {
    int tok  = blockIdx.x * 8 + (threadIdx.x >> 5);   // 0..32767
    int lane = threadIdx.x & 31;

    int idx  = x[tok];
    float sw = sqrtf(g_w[tok]);

    const float* a_ = amp + (size_t)idx * ND;
    const float* p_ = pha + (size_t)idx * ND;
    float* dst = g_v + (size_t)tok * 2 * NDP;

    float a0 = a_[lane];
    float p0 = p_[lane];
    float a1 = 0.f, p1 = 0.f;
    if (lane < ND - 32) { a1 = a_[lane + 32]; p1 = p_[lane + 32]; }

    float s, c;
    __sincosf(p0, &s, &c);
    float amp0 = a0 * sw;
    dst[lane]       = amp0 * c;
    dst[NDP + lane] = amp0 * s;

    if (lane < NDP - 32) {                 // lanes 0..19 cover d=32..51
        float vr1 = 0.f, vi1 = 0.f;
        if (lane < ND - 32) {              // lanes 0..17: real data d=32..49
            __sincosf(p1, &s, &c);
            float amp1 = a1 * sw;
            vr1 = amp1 * c;
            vi1 = amp1 * s;
        }
        dst[32 + lane]       = vr1;        // d=50,51 -> zeros
        dst[NDP + 32 + lane] = vi1;
    }
}

// ---------------- K3: main contraction ----------------
// grid = NB * NCHUNK CTAs, 128 threads. Thread m owns kernel row m in registers
// (packed f32x2). Token vectors broadcast from SMEM. Per token:
//   P = sum kr*vr, Q = sum ki*vi, R = sum kr*vi, S = sum ki*vr
//   ar = P+Q, ai = R-S;  acc += ar^2 + ai^2   (sqrt(w) already folded into v)
__global__ void __launch_bounds__(128) k_main() {
    __shared__ float4 sv[LCHUNK * 2 * NDP / 4];   // 32 * 104 floats = 13312 B

    int b = blockIdx.x >> 4;     // / NCHUNK
    int c = blockIdx.x & 15;     // % NCHUNK
    int m = threadIdx.x;

    // load this thread's kernel row into registers as f32x2 pairs
    unsigned long long kr2[NDP / 2], ki2[NDP / 2];
    {
        const ulonglong2* kp = (const ulonglong2*)(g_kr + m * NDP);
        const ulonglong2* kq = (const ulonglong2*)(g_ki + m * NDP);
#pragma unroll
        for (int i = 0; i < NDP / 4; i++) {
            ulonglong2 t = kp[i]; kr2[2 * i] = t.x; kr2[2 * i + 1] = t.y;
            ulonglong2 u = kq[i]; ki2[2 * i] = u.x; ki2[2 * i + 1] = u.y;
        }
    }

    // cooperatively stage the token tile into shared memory
    {
        const float4* src = (const float4*)(g_v + (size_t)(b * NL + c * LCHUNK) * 2 * NDP);
        for (int i = m; i < LCHUNK * 2 * NDP / 4; i += 128) sv[i] = src[i];
    }
    __syncthreads();

    float acc = 0.f;
    const float* svf = (const float*)sv;

#pragma unroll 2
    for (int l = 0; l < LCHUNK; l++) {
        const ulonglong2* vr = (const ulonglong2*)(svf + l * 2 * NDP);
        const ulonglong2* vi = (const ulonglong2*)(svf + l * 2 * NDP + NDP);
        unsigned long long P = 0ull, Q = 0ull, R = 0ull, S = 0ull;
#pragma unroll
        for (int k = 0; k < NDP / 4; k++) {
            ulonglong2 r  = vr[k];     // two packed vr pairs (broadcast LDS.128)
            ulonglong2 ii = vi[k];     // two packed vi pairs
            FMA2(P, kr2[2 * k],     r.x);
            FMA2(Q, ki2[2 * k],     ii.x);
            FMA2(R, kr2[2 * k],     ii.x);
            FMA2(S, ki2[2 * k],     r.x);
            FMA2(P, kr2[2 * k + 1], r.y);
            FMA2(Q, ki2[2 * k + 1], ii.y);
            FMA2(R, kr2[2 * k + 1], ii.y);
            FMA2(S, ki2[2 * k + 1], r.y);
        }
        float2 pP = up2(P), pQ = up2(Q), pR = up2(R), pS = up2(S);
        float ar = (pP.x + pP.y) + (pQ.x + pQ.y);
        float ai = (pR.x + pR.y) - (pS.x + pS.y);
        acc = fmaf(ar, ar, acc);
        acc = fmaf(ai, ai, acc);
    }

    g_part[(c * NB + b) * NM + m] = acc;
}

// ---------------- K4: reduce partial sums over chunks ----------------
__global__ void k_reduce(float* __restrict__ out) {
    int i = blockIdx.x * 256 + threadIdx.x;   // 0..8191
    float s = 0.f;
#pragma unroll
    for (int c = 0; c < NCHUNK; c++) s += g_part[c * NB * NM + i];
    out[i] = s;
}

// ---------------- entry point ----------------
extern "C" void kernel_launch(void* const* d_in, const int* in_sizes, int n_in,
                              void* d_out, int out_size) {
    const int*   x   = (const int*)  d_in[0];   // [B, L] int32
    const float* amp = (const float*)d_in[1];   // [VOCAB, D]
    const float* pha = (const float*)d_in[2];   // [VOCAB, D]
    const float* mix = (const float*)d_in[3];   // [VOCAB, 1]
    const float* kr  = (const float*)d_in[4];   // [M, D]
    const float* ki  = (const float*)d_in[5];   // [M, D]
    float* out = (float*)d_out;                 // [B, M]

    k_norm<<<1, NM>>>(kr, ki);
    k_softmax<<<NB, NL>>>(x, mix);
    k_gather<<<NB * NL / 8, 256>>>(x, amp, pha);
    k_main<<<NB * NCHUNK, 128>>>();
    k_reduce<<<NB * NM / 256, 256>>>(out);
}

// round 11
// speedup vs baseline: 1.1170x; 1.1170x over previous
#include <cuda_runtime.h>
#include <cstdint>
#include <cstddef>

// Problem shapes (fixed by the dataset)
#define NB 64          // batch
#define NL 512         // sequence length
#define ND 50          // embedding dim
#define NDP 56         // padded dim (halves of 28 floats = 112B, 16B-aligned)
#define NDH 28         // half-dim per lane group
#define NM 128         // number of measurement kernels
#define LCHUNK 64      // tokens per k_main CTA
#define NCHUNK (NL / LCHUNK)   // 8
#define TROW (2 * NDP) // floats per token row in g_v (vr[56] | vi[56])

// ---------------- device-global scratch (no runtime allocation) ----------------
__device__ float g_w[NB * NL];                              // softmax weights
__device__ __align__(16) float g_kr[NM * NDP];              // normalized kernel_real, padded
__device__ __align__(16) float g_ki[NM * NDP];              // normalized kernel_imag, padded
__device__ float4 g_v4[(size_t)NB * NL * TROW / 4];         // sqrt(w)-scaled vr|vi per token (~14.7MB)
__device__ float g_part[NCHUNK * NB * NM];                  // per-chunk partial sums

// packed f32x2 helpers (Blackwell sm_103a)
__device__ __forceinline__ float2 up2(unsigned long long v) {
    float2 r;
    asm("mov.b64 {%0, %1}, %2;" : "=f"(r.x), "=f"(r.y) : "l"(v));
    return r;
}
#define FMA2(d, a, b) asm("fma.rn.f32x2 %0, %1, %2, %0;" : "+l"(d) : "l"(a), "l"(b))

// ---------------- K1: softmax over sequence per batch (+ fused kernel-norm) ----------------
// blocks 0..63: softmax for batch b. block 64: normalize measurement kernels.
__global__ void k_softmax(const int* __restrict__ x, const float* __restrict__ mix,
                          const float* __restrict__ kr, const float* __restrict__ ki) {
    int b = blockIdx.x;
    int t = threadIdx.x;

    if (b == NB) {
        // kernel normalization, pad D 50 -> 56 with zeros
        if (t < NM) {
            float s = 0.f;
#pragma unroll
            for (int d = 0; d < ND; d++) {
                float a = kr[t * ND + d];
                float c = ki[t * ND + d];
                s = fmaf(a, a, s);
                s = fmaf(c, c, s);
            }
            float rn = rsqrtf(s);
#pragma unroll
            for (int d = 0; d < NDP; d++) {
                g_kr[t * NDP + d] = (d < ND) ? kr[t * ND + d] * rn : 0.f;
                g_ki[t * NDP + d] = (d < ND) ? ki[t * ND + d] * rn : 0.f;
            }
        }
        return;
    }

    float v = mix[x[b * NL + t]];
    __shared__ float red[16];

    // block max
    float m = v;
#pragma unroll
    for (int o = 16; o > 0; o >>= 1) m = fmaxf(m, __shfl_xor_sync(0xffffffffu, m, o));
    if ((t & 31) == 0) red[t >> 5] = m;
    __syncthreads();
    if (t < 16) {
        float mm = red[t];
#pragma unroll
        for (int o = 8; o > 0; o >>= 1) mm = fmaxf(mm, __shfl_xor_sync(0x0000ffffu, mm, o));
        if (t == 0) red[0] = mm;
    }
    __syncthreads();
    float vmax = red[0];
    __syncthreads();

    // block sum of exp
    float e = __expf(v - vmax);
    float s = e;
#pragma unroll
    for (int o = 16; o > 0; o >>= 1) s += __shfl_xor_sync(0xffffffffu, s, o);
    if ((t & 31) == 0) red[t >> 5] = s;
    __syncthreads();
    if (t < 16) {
        float ss = red[t];
#pragma unroll
        for (int o = 8; o > 0; o >>= 1) ss += __shfl_xor_sync(0x0000ffffu, ss, o);
        if (t == 0) red[0] = ss;
    }
    __syncthreads();
    g_w[b * NL + t] = e / red[0];
}

// ---------------- K2: gather + convert: v = sqrt(w) * amp * exp(i*pha) ----------------
// one warp per token; lane covers d=lane and d=lane+32; pad d=50..55 with zeros
__global__ void k_gather(const int* __restrict__ x,
                         const float* __restrict__ amp,
                         const float* __restrict__ pha) {
    int tok  = blockIdx.x * 8 + (threadIdx.x >> 5);   // 0..32767
    int lane = threadIdx.x & 31;

    int idx  = x[tok];
    float sw = sqrtf(g_w[tok]);

    const float* a_ = amp + (size_t)idx * ND;
    const float* p_ = pha + (size_t)idx * ND;
    float* dst = (float*)g_v4 + (size_t)tok * TROW;

    float a0 = a_[lane];
    float p0 = p_[lane];
    float a1 = 0.f, p1 = 0.f;
    if (lane < ND - 32) { a1 = a_[lane + 32]; p1 = p_[lane + 32]; }

    float s, c;
    __sincosf(p0, &s, &c);
    float amp0 = a0 * sw;
    dst[lane]       = amp0 * c;
    dst[NDP + lane] = amp0 * s;

    if (lane < NDP - 32) {                 // lanes 0..23 cover d=32..55
        float vr1 = 0.f, vi1 = 0.f;
        if (lane < ND - 32) {              // lanes 0..17: real data d=32..49
            __sincosf(p1, &s, &c);
            float amp1 = a1 * sw;
            vr1 = amp1 * c;
            vi1 = amp1 * s;
        }
        dst[32 + lane]       = vr1;        // d=50..55 -> zeros
        dst[NDP + 32 + lane] = vi1;
    }
}

// ---------------- K3: main contraction (half-row split) ----------------
// CTA = 256 thr (8 warps). Warp w owns m = w*16 + (lane&15); lane group h = lane>>4
// owns dim half [h*28, h*28+28). Row half lives in 56 registers (28 x f32x2).
// Per token: P=sum kr*vr, Q=sum ki*vi, R=sum kr*vi, S=sum ki*vr over own half;
// combine halves via shfl.xor 16; acc += ar^2 + ai^2 (sqrt(w) folded into v).
__global__ void __launch_bounds__(256, 2) k_main() {
    __shared__ float4 sv4[LCHUNK * TROW / 4];   // 64 * 112 floats = 28672 B

    int b = blockIdx.x >> 3;     // / NCHUNK
    int c = blockIdx.x & 7;      // % NCHUNK
    int t = threadIdx.x;
    int lane = t & 31;
    int h  = lane >> 4;                    // dim half
    int mi = ((t >> 5) << 4) | (lane & 15);  // m index 0..127

    // load this thread's half-row into registers as f32x2 pairs
    unsigned long long kr2[NDH / 2], ki2[NDH / 2];
    {
        const ulonglong2* kp = (const ulonglong2*)(g_kr + mi * NDP + h * NDH);
        const ulonglong2* kq = (const ulonglong2*)(g_ki + mi * NDP + h * NDH);
#pragma unroll
        for (int i = 0; i < NDH / 4; i++) {
            ulonglong2 a = kp[i]; kr2[2 * i] = a.x; kr2[2 * i + 1] = a.y;
            ulonglong2 d = kq[i]; ki2[2 * i] = d.x; ki2[2 * i + 1] = d.y;
        }
    }

    // cooperatively stage the token tile into shared memory (coalesced float4)
    {
        const float4* src = g_v4 + (size_t)(b * NL + c * LCHUNK) * TROW / 4;
#pragma unroll
        for (int i = t; i < LCHUNK * TROW / 4; i += 256) sv4[i] = src[i];
    }
    __syncthreads();

    float acc = 0.f;
    const float* svf = (const float*)sv4;

#pragma unroll 2
    for (int l = 0; l < LCHUNK; l++) {
        const ulonglong2* vr = (const ulonglong2*)(svf + l * TROW + h * NDH);
        const ulonglong2* vi = (const ulonglong2*)(svf + l * TROW + NDP + h * NDH);
        unsigned long long P = 0ull, Q = 0ull, R = 0ull, S = 0ull;
#pragma unroll
        for (int k = 0; k < NDH / 4; k++) {
            ulonglong2 r  = vr[k];    // two packed vr pairs (LDS.128, 2-addr broadcast)
            ulonglong2 ii = vi[k];    // two packed vi pairs
            FMA2(P, kr2[2 * k],     r.x);
            FMA2(Q, ki2[2 * k],     ii.x);
            FMA2(R, kr2[2 * k],     ii.x);
            FMA2(S, ki2[2 * k],     r.x);
            FMA2(P, kr2[2 * k + 1], r.y);
            FMA2(Q, ki2[2 * k + 1], ii.y);
            FMA2(R, kr2[2 * k + 1], ii.y);
            FMA2(S, ki2[2 * k + 1], r.y);
        }
        float2 pP = up2(P), pQ = up2(Q), pR = up2(R), pS = up2(S);
        float arh = (pP.x + pP.y) + (pQ.x + pQ.y);
        float aih = (pR.x + pR.y) - (pS.x + pS.y);
        float ar = arh + __shfl_xor_sync(0xffffffffu, arh, 16);
        float ai = aih + __shfl_xor_sync(0xffffffffu, aih, 16);
        acc = fmaf(ar, ar, acc);
        acc = fmaf(ai, ai, acc);
    }

    if (h == 0) g_part[(c * NB + b) * NM + mi] = acc;
}

// ---------------- K4: reduce partial sums over chunks ----------------
__global__ void k_reduce(float* __restrict__ out) {
    int i = blockIdx.x * 256 + threadIdx.x;   // 0..8191
    float s = 0.f;
#pragma unroll
    for (int c = 0; c < NCHUNK; c++) s += g_part[c * NB * NM + i];
    out[i] = s;
}

// ---------------- entry point ----------------
extern "C" void kernel_launch(void* const* d_in, const int* in_sizes, int n_in,
                              void* d_out, int out_size) {
    const int*   x   = (const int*)  d_in[0];   // [B, L] int32
    const float* amp = (const float*)d_in[1];   // [VOCAB, D]
    const float* pha = (const float*)d_in[2];   // [VOCAB, D]
    const float* mix = (const float*)d_in[3];   // [VOCAB, 1]
    const float* kr  = (const float*)d_in[4];   // [M, D]
    const float* ki  = (const float*)d_in[5];   // [M, D]
    float* out = (float*)d_out;                 // [B, M]

    k_softmax<<<NB + 1, NL>>>(x, mix, kr, ki);   // +1 block does kernel normalization
    k_gather<<<NB * NL / 8, 256>>>(x, amp, pha);
    k_main<<<NB * NCHUNK, 256>>>();
    k_reduce<<<NB * NM / 256, 256>>>(out);
}

// round 12
// speedup vs baseline: 1.1176x; 1.0005x over previous
#include <cuda_runtime.h>
#include <cstdint>
#include <cstddef>

// Problem shapes (fixed by the dataset)
#define NB 64          // batch
#define NL 512         // sequence length
#define ND 50          // embedding dim
#define NDP 56         // padded dim (halves of 28 floats = 112B, 16B-aligned)
#define NDH 28         // half-dim per lane group
#define NM 128         // number of measurement kernels
#define LCHUNK 64      // tokens per k_main CTA
#define NCHUNK (NL / LCHUNK)   // 8
#define TROW (2 * NDP) // floats per token row in g_v (vr[56] | vi[56])

// ---------------- device-global scratch (no runtime allocation) ----------------
__device__ float g_w[NB * NL];                              // softmax weights
__device__ __align__(16) float g_kr[NM * NDP];              // normalized kernel_real, padded
__device__ __align__(16) float g_ki[NM * NDP];              // normalized kernel_imag, padded
__device__ float4 g_v4[(size_t)NB * NL * TROW / 4];         // sqrt(w)-scaled vr|vi per token (~14.7MB)
__device__ float g_part[NCHUNK * NB * NM];                  // per-chunk partial sums

// packed f32x2 helpers (Blackwell sm_103a)
__device__ __forceinline__ float2 up2(unsigned long long v) {
    float2 r;
    asm("mov.b64 {%0, %1}, %2;" : "=f"(r.x), "=f"(r.y) : "l"(v));
    return r;
}
#define FMA2(d, a, b) asm("fma.rn.f32x2 %0, %1, %2, %0;" : "+l"(d) : "l"(a), "l"(b))

// ---------------- K1: softmax over sequence per batch (+ fused kernel-norm) ----------------
// blocks 0..63: softmax for batch b. block 64: normalize measurement kernels.
__global__ void k_softmax(const int* __restrict__ x, const float* __restrict__ mix,
                          const float* __restrict__ kr, const float* __restrict__ ki) {
    int b = blockIdx.x;
    int t = threadIdx.x;

    if (b == NB) {
        // kernel normalization, pad D 50 -> 56 with zeros
        if (t < NM) {
            float s = 0.f;
#pragma unroll
            for (int d = 0; d < ND; d++) {
                float a = kr[t * ND + d];
                float c = ki[t * ND + d];
                s = fmaf(a, a, s);
                s = fmaf(c, c, s);
            }
            float rn = rsqrtf(s);
#pragma unroll
            for (int d = 0; d < NDP; d++) {
                g_kr[t * NDP + d] = (d < ND) ? kr[t * ND + d] * rn : 0.f;
                g_ki[t * NDP + d] = (d < ND) ? ki[t * ND + d] * rn : 0.f;
            }
        }
        return;
    }

    float v = mix[x[b * NL + t]];
    __shared__ float red[16];

    // block max
    float m = v;
#pragma unroll
    for (int o = 16; o > 0; o >>= 1) m = fmaxf(m, __shfl_xor_sync(0xffffffffu, m, o));
    if ((t & 31) == 0) red[t >> 5] = m;
    __syncthreads();
    if (t < 16) {
        float mm = red[t];
#pragma unroll
        for (int o = 8; o > 0; o >>= 1) mm = fmaxf(mm, __shfl_xor_sync(0x0000ffffu, mm, o));
        if (t == 0) red[0] = mm;
    }
    __syncthreads();
    float vmax = red[0];
    __syncthreads();

    // block sum of exp
    float e = __expf(v - vmax);
    float s = e;
#pragma unroll
    for (int o = 16; o > 0; o >>= 1) s += __shfl_xor_sync(0xffffffffu, s, o);
    if ((t & 31) == 0) red[t >> 5] = s;
    __syncthreads();
    if (t < 16) {
        float ss = red[t];
#pragma unroll
        for (int o = 8; o > 0; o >>= 1) ss += __shfl_xor_sync(0x0000ffffu, ss, o);
        if (t == 0) red[0] = ss;
    }
    __syncthreads();
    g_w[b * NL + t] = e / red[0];
}

// ---------------- K2: gather + convert: v = sqrt(w) * amp * exp(i*pha) ----------------
// one warp per token; lane covers d=lane and d=lane+32; pad d=50..55 with zeros
__global__ void k_gather(const int* __restrict__ x,
                         const float* __restrict__ amp,
                         const float* __restrict__ pha) {
    int tok  = blockIdx.x * 8 + (threadIdx.x >> 5);   // 0..32767
    int lane = threadIdx.x & 31;

    int idx  = x[tok];
    float sw = sqrtf(g_w[tok]);

    const float* a_ = amp + (size_t)idx * ND;
    const float* p_ = pha + (size_t)idx * ND;
    float* dst = (float*)g_v4 + (size_t)tok * TROW;

    float a0 = a_[lane];
    float p0 = p_[lane];
    float a1 = 0.f, p1 = 0.f;
    if (lane < ND - 32) { a1 = a_[lane + 32]; p1 = p_[lane + 32]; }

    float s, c;
    __sincosf(p0, &s, &c);
    float amp0 = a0 * sw;
    dst[lane]       = amp0 * c;
    dst[NDP + lane] = amp0 * s;

    if (lane < NDP - 32) {                 // lanes 0..23 cover d=32..55
        float vr1 = 0.f, vi1 = 0.f;
        if (lane < ND - 32) {              // lanes 0..17: real data d=32..49
            __sincosf(p1, &s, &c);
            float amp1 = a1 * sw;
            vr1 = amp1 * c;
            vi1 = amp1 * s;
        }
        dst[32 + lane]       = vr1;        // d=50..55 -> zeros
        dst[NDP + 32 + lane] = vi1;
    }
}

// ---------------- K3: main contraction (half-row split) ----------------
// CTA = 256 thr (8 warps). Warp w owns m = w*16 + (lane&15); lane group h = lane>>4
// owns dim half [h*28, h*28+28). Row half lives in 56 registers (28 x f32x2).
// Per token: P=sum kr*vr, Q=sum ki*vi, R=sum kr*vi, S=sum ki*vr over own half;
// combine halves via shfl.xor 16; acc += ar^2 + ai^2 (sqrt(w) folded into v).
__global__ void __launch_bounds__(256, 2) k_main() {
    __shared__ float4 sv4[LCHUNK * TROW / 4];   // 64 * 112 floats = 28672 B

    int b = blockIdx.x >> 3;     // / NCHUNK
    int c = blockIdx.x & 7;      // % NCHUNK
    int t = threadIdx.x;
    int lane = t & 31;
    int h  = lane >> 4;                    // dim half
    int mi = ((t >> 5) << 4) | (lane & 15);  // m index 0..127

    // load this thread's half-row into registers as f32x2 pairs
    unsigned long long kr2[NDH / 2], ki2[NDH / 2];
    {
        const ulonglong2* kp = (const ulonglong2*)(g_kr + mi * NDP + h * NDH);
        const ulonglong2* kq = (const ulonglong2*)(g_ki + mi * NDP + h * NDH);
#pragma unroll
        for (int i = 0; i < NDH / 4; i++) {
            ulonglong2 a = kp[i]; kr2[2 * i] = a.x; kr2[2 * i + 1] = a.y;
            ulonglong2 d = kq[i]; ki2[2 * i] = d.x; ki2[2 * i + 1] = d.y;
        }
    }

    // cooperatively stage the token tile into shared memory (coalesced float4)
    {
        const float4* src = g_v4 + (size_t)(b * NL + c * LCHUNK) * TROW / 4;
#pragma unroll
        for (int i = t; i < LCHUNK * TROW / 4; i += 256) sv4[i] = src[i];
    }
    __syncthreads();

    float acc = 0.f;
    const float* svf = (const float*)sv4;

#pragma unroll 2
    for (int l = 0; l < LCHUNK; l++) {
        const ulonglong2* vr = (const ulonglong2*)(svf + l * TROW + h * NDH);
        const ulonglong2* vi = (const ulonglong2*)(svf + l * TROW + NDP + h * NDH);
        unsigned long long P = 0ull, Q = 0ull, R = 0ull, S = 0ull;
#pragma unroll
        for (int k = 0; k < NDH / 4; k++) {
            ulonglong2 r  = vr[k];    // two packed vr pairs (LDS.128, 2-addr broadcast)
            ulonglong2 ii = vi[k];    // two packed vi pairs
            FMA2(P, kr2[2 * k],     r.x);
            FMA2(Q, ki2[2 * k],     ii.x);
            FMA2(R, kr2[2 * k],     ii.x);
            FMA2(S, ki2[2 * k],     r.x);
            FMA2(P, kr2[2 * k + 1], r.y);
            FMA2(Q, ki2[2 * k + 1], ii.y);
            FMA2(R, kr2[2 * k + 1], ii.y);
            FMA2(S, ki2[2 * k + 1], r.y);
        }
        float2 pP = up2(P), pQ = up2(Q), pR = up2(R), pS = up2(S);
        float arh = (pP.x + pP.y) + (pQ.x + pQ.y);
        float aih = (pR.x + pR.y) - (pS.x + pS.y);
        float ar = arh + __shfl_xor_sync(0xffffffffu, arh, 16);
        float ai = aih + __shfl_xor_sync(0xffffffffu, aih, 16);
        acc = fmaf(ar, ar, acc);
        acc = fmaf(ai, ai, acc);
    }

    if (h == 0) g_part[(c * NB + b) * NM + mi] = acc;
}

// ---------------- K4: reduce partial sums over chunks ----------------
__global__ void k_reduce(float* __restrict__ out) {
    int i = blockIdx.x * 256 + threadIdx.x;   // 0..8191
    float s = 0.f;
#pragma unroll
    for (int c = 0; c < NCHUNK; c++) s += g_part[c * NB * NM + i];
    out[i] = s;
}

// ---------------- entry point ----------------
extern "C" void kernel_launch(void* const* d_in, const int* in_sizes, int n_in,
                              void* d_out, int out_size) {
    const int*   x   = (const int*)  d_in[0];   // [B, L] int32
    const float* amp = (const float*)d_in[1];   // [VOCAB, D]
    const float* pha = (const float*)d_in[2];   // [VOCAB, D]
    const float* mix = (const float*)d_in[3];   // [VOCAB, 1]
    const float* kr  = (const float*)d_in[4];   // [M, D]
    const float* ki  = (const float*)d_in[5];   // [M, D]
    float* out = (float*)d_out;                 // [B, M]

    k_softmax<<<NB + 1, NL>>>(x, mix, kr, ki);   // +1 block does kernel normalization
    k_gather<<<NB * NL / 8, 256>>>(x, amp, pha);
    k_main<<<NB * NCHUNK, 256>>>();
    k_reduce<<<NB * NM / 256, 256>>>(out);
}